// round 15
// baseline (speedup 1.0000x reference)
#include <cuda_runtime.h>
#include <cstdint>

// ---------------- problem constants ----------------
#define BB   16
#define DD   512
#define TT   2048
#define KK   1024
#define NN   (BB*TT)          // 32768
#define NQ   (BB*DD*TT)       // 16777216

// ---------------- pass-1 tiling (R14-proven, hi-only, 3-buffer) ---------------
#define M_TILE   128
#define N_TILE   128
#define NT_COUNT (KK / N_TILE)        // 8
#define D_STAGE  32
#define STAGES_PER_NT (DD / D_STAGE)  // 16
#define TOT_STAGES (NT_COUNT * STAGES_PER_NT)  // 128
#define THREADS  256

// smem strides (floats):
// A [d][m]: stride 136 -> LDS bank = 8q + r4 (all 32 distinct)
// B [n][d]: stride 36  -> LDS bank = 4r4 + q (all 32 distinct)
#define A_LD 136
#define B_LD 36
#define A_PLANE (D_STAGE * A_LD * 4)   // 17408
#define B_PLANE (N_TILE * B_LD * 4)    // 18432
#define OFF_B   A_PLANE
#define BUF_BYTES (A_PLANE + B_PLANE)  // 35840
#define DYN_SMEM  (3 * BUF_BYTES)      // 107520 -> 2 CTAs/SM (215K < 227K)

typedef unsigned long long ull;

// ---------------- PTX helpers (arch-neutral: compute_80+) ----------------
__device__ __forceinline__ uint32_t smem_u32(const void* p) {
    uint32_t a;
    asm("{ .reg .u64 t; cvta.to.shared.u64 t, %1; cvt.u32.u64 %0, t; }" : "=r"(a) : "l"(p));
    return a;
}
#define CP_ASYNC16(dst, src) asm volatile("cp.async.cg.shared.global [%0], [%1], 16;" :: "r"(dst), "l"(src))
#define CP_COMMIT()          asm volatile("cp.async.commit_group;" ::: "memory")
#define CP_WAIT1()           asm volatile("cp.async.wait_group 1;" ::: "memory")
#define CP_WAIT0()           asm volatile("cp.async.wait_group 0;" ::: "memory")

__device__ __forceinline__ uint32_t to_tf32(float v) {
    uint32_t r;
    asm("cvt.rna.tf32.f32 %0, %1;" : "=r"(r) : "f"(v));
    return r;
}
#define MMA_TF32(c0,c1,c2,c3, a0,a1,a2,a3, b0,b1) \
    asm volatile("mma.sync.aligned.m16n8k8.row.col.f32.tf32.tf32.f32 " \
        "{%0,%1,%2,%3}, {%4,%5,%6,%7}, {%8,%9}, {%0,%1,%2,%3};" \
        : "+f"(c0), "+f"(c1), "+f"(c2), "+f"(c3) \
        : "r"(a0), "r"(a1), "r"(a2), "r"(a3), "r"(b0), "r"(b1))

// ---------------- device scratch (static: allocation-free rule) ---------------
__device__ float  g_zHi[(size_t)NQ];       // 64 MB: tf32-hi of z, [b][d][t]
__device__ float  g_zT[(size_t)NQ];        // 64 MB: exact fp32 z, [n][d]
__device__ float  g_dist[(size_t)NN*KK];   // 128 MB: approx dists
__device__ float  g_cbHi[KK * DD];         // 2 MB: tf32-hi codebook [k][d]
__device__ float  g_cbT[DD * KK];          // gather cache [d][k]
__device__ float  g_wsq[KK];
__device__ float  g_zsq[NN];
__device__ int    g_idx[NN];
__device__ int    g_wsqmax_bits;           // max wsq (float bits; atomicMax idempotent)
__device__ double g_loss;

// ---------------- K0a: codebook prep ------------------------------------------
__global__ void prep_codebook(const float* __restrict__ cb) {
    int k   = blockIdx.x;
    int tid = threadIdx.x;      // 128
    float s = 0.f;
    for (int d = tid; d < DD; d += 128) {
        float v = cb[(size_t)k * DD + d];
        g_cbT[(size_t)d * KK + k]  = v;
        g_cbHi[(size_t)k * DD + d] = __uint_as_float(to_tf32(v));
        s += v * v;
    }
    #pragma unroll
    for (int o = 16; o; o >>= 1) s += __shfl_xor_sync(0xffffffffu, s, o);
    __shared__ float ws[4];
    if ((tid & 31) == 0) ws[tid >> 5] = s;
    __syncthreads();
    if (tid == 0) {
        float w = (ws[0] + ws[1]) + (ws[2] + ws[3]);
        g_wsq[k] = w;
        atomicMax(&g_wsqmax_bits, __float_as_int(w));
        if (k == 0) g_loss = 0.0;
    }
}

// ---------------- K0b: z -> hi plane ([b][d][t]) + exact transposed ([n][d]) --
__global__ void transpose_split(const float* __restrict__ z) {
    __shared__ float tile[32][33];
    int b  = blockIdx.z;
    int d0 = blockIdx.y * 32;
    int t0 = blockIdx.x * 32;
    int tx = threadIdx.x, ty = threadIdx.y;
    #pragma unroll
    for (int i = ty; i < 32; i += 8) {
        size_t off = ((size_t)b * DD + d0 + i) * TT + t0 + tx;
        float v = z[off];
        g_zHi[off] = __uint_as_float(to_tf32(v));
        tile[i][tx] = v;
    }
    __syncthreads();
    #pragma unroll
    for (int i = ty; i < 32; i += 8)
        g_zT[(size_t)(b * TT + t0 + i) * DD + d0 + tx] = tile[tx][i];
}

// ---------------- K0c: per-row |z|^2 ------------------------------------------
__global__ void compute_zsq(const float* __restrict__ z) {
    int n0 = blockIdx.x * 128;
    int b  = n0 >> 11;
    int t  = (n0 & (TT - 1)) + threadIdx.x;
    const float* zb = z + (size_t)b * DD * TT + t;
    float s0 = 0.f, s1 = 0.f, s2 = 0.f, s3 = 0.f;
    #pragma unroll 4
    for (int d = 0; d < DD; d += 4) {
        float v0 = zb[(size_t)(d + 0) * TT];
        float v1 = zb[(size_t)(d + 1) * TT];
        float v2 = zb[(size_t)(d + 2) * TT];
        float v3 = zb[(size_t)(d + 3) * TT];
        s0 = fmaf(v0, v0, s0);
        s1 = fmaf(v1, v1, s1);
        s2 = fmaf(v2, v2, s2);
        s3 = fmaf(v3, v3, s3);
    }
    g_zsq[n0 + threadIdx.x] = (s0 + s1) + (s2 + s3);
}

// ---------------- K1: pass-1 TF32 hi-only GEMM -> dist matrix -----------------
// 3-buffer cp.async pipeline, ONE __syncthreads per stage.
__global__ __launch_bounds__(THREADS, 2)
void vq_pass1()
{
    extern __shared__ char dyn[];

    const uint32_t dynb = smem_u32(dyn);
    int tid  = threadIdx.x;
    int lane = tid & 31;
    int wid  = tid >> 5;
    int q    = lane & 3;
    int r4   = lane >> 2;
    int warpM  = (wid & 3) * 32;   // 4 M-bands of 32
    int warpNb = wid >> 2;         // 2 N-bands
    int warpN  = warpNb * 64;

    int n0 = blockIdx.x * M_TILE;  // grid = 256 (one wave at 2 CTAs/SM)
    int b  = n0 >> 11;
    int t0 = n0 & (TT - 1);
    size_t zoff = (size_t)b * DD * TT + t0;

    float zsqr[4];   // rows warpM + 16mi + 8h + r4
    #pragma unroll
    for (int mi = 0; mi < 2; mi++)
        #pragma unroll
        for (int h = 0; h < 2; h++)
            zsqr[mi * 2 + h] = g_zsq[n0 + warpM + 16 * mi + 8 * h + r4];

    float acc[2][8][4];   // (mi, nf, e) = 64 floats
    #pragma unroll
    for (int mi = 0; mi < 2; mi++)
        #pragma unroll
        for (int nf = 0; nf < 8; nf++)
            #pragma unroll
            for (int e = 0; e < 4; e++) acc[mi][nf][e] = 0.f;

    // cp.async decomposition: per plane 1024 x16B chunks, 4/thread
    int aRow[4], aC[4], bN[4], bCd[4];
    #pragma unroll
    for (int i = 0; i < 4; i++) {
        int u = tid + i * 256;
        aRow[i] = u >> 5;          // 0..31  (d row)
        aC[i]   = u & 31;          // 16B chunk along m
        bN[i]   = u >> 3;          // 0..127 (n row)
        bCd[i]  = u & 7;           // 16B chunk along d
    }

    auto load_stage = [&](int gs, int buf) {
        int d0  = (gs & (STAGES_PER_NT - 1)) * D_STAGE;
        int kb0 = (gs >> 4) * N_TILE;
        uint32_t bb = dynb + buf * BUF_BYTES;
        #pragma unroll
        for (int i = 0; i < 4; i++) {
            CP_ASYNC16(bb + aRow[i] * (A_LD * 4) + aC[i] * 16,
                       g_zHi + zoff + (size_t)(d0 + aRow[i]) * TT + aC[i] * 4);
            CP_ASYNC16(bb + OFF_B + bN[i] * (B_LD * 4) + bCd[i] * 16,
                       g_cbHi + (size_t)(kb0 + bN[i]) * DD + d0 + bCd[i] * 4);
        }
        CP_COMMIT();
    };

    load_stage(0, 0);
    load_stage(1, 1);

    #pragma unroll 1
    for (int gs = 0; gs < TOT_STAGES; gs++) {
        if (gs + 1 < TOT_STAGES) { CP_WAIT1(); } else { CP_WAIT0(); }
        __syncthreads();   // stage gs visible to all; all reads of buf (gs-1)%3 done
        if (gs + 2 < TOT_STAGES) load_stage(gs + 2, (gs + 2) % 3);

        int cur = gs % 3;
        const uint32_t* As = (const uint32_t*)(dyn + cur * BUF_BYTES);
        const uint32_t* Bs = (const uint32_t*)(dyn + cur * BUF_BYTES + OFF_B);

        #pragma unroll
        for (int j = 0; j < 4; j++) {
            uint32_t ah[2][4];
            #pragma unroll
            for (int mi = 0; mi < 2; mi++) {
                int rm = warpM + 16 * mi + r4;
                #pragma unroll
                for (int e = 0; e < 4; e++) {
                    int dd = 8 * j + q + (e >> 1) * 4;
                    int mm = rm + (e & 1) * 8;
                    ah[mi][e] = As[dd * A_LD + mm];
                }
            }
            #pragma unroll
            for (int nf = 0; nf < 8; nf++) {
                int nn = warpN + 8 * nf + r4;
                uint32_t b0 = Bs[nn * B_LD + 8 * j + q];
                uint32_t b1 = Bs[nn * B_LD + 8 * j + q + 4];
                #pragma unroll
                for (int mi = 0; mi < 2; mi++) {
                    float* c = acc[mi][nf];
                    MMA_TF32(c[0], c[1], c[2], c[3],
                             ah[mi][0], ah[mi][1], ah[mi][2], ah[mi][3], b0, b1);
                }
            }
        }

        // n-tile boundary: store dists, reset acc (register-only, no barrier)
        if ((gs & (STAGES_PER_NT - 1)) == STAGES_PER_NT - 1) {
            int kb0 = (gs >> 4) * N_TILE;
            #pragma unroll
            for (int mi = 0; mi < 2; mi++) {
                #pragma unroll
                for (int h = 0; h < 2; h++) {
                    int n = n0 + warpM + 16 * mi + 8 * h + r4;
                    float zs = zsqr[mi * 2 + h];
                    #pragma unroll
                    for (int nf = 0; nf < 8; nf++) {
                        int col = kb0 + warpN + 8 * nf + 2 * q;
                        float w0 = __ldg(&g_wsq[col]);
                        float w1 = __ldg(&g_wsq[col + 1]);
                        float v0 = __fadd_rn(__fsub_rn(zs, __fmul_rn(2.0f, acc[mi][nf][2 * h + 0])), w0);
                        float v1 = __fadd_rn(__fsub_rn(zs, __fmul_rn(2.0f, acc[mi][nf][2 * h + 1])), w1);
                        *(float2*)(g_dist + (size_t)n * KK + col) = make_float2(v0, v1);
                    }
                }
            }
            #pragma unroll
            for (int mi = 0; mi < 2; mi++)
                #pragma unroll
                for (int nf = 0; nf < 8; nf++)
                    #pragma unroll
                    for (int e = 0; e < 4; e++) acc[mi][nf][e] = 0.f;
        }
    }
}

// ---------------- K2: refine — warp-per-row exact argmin ----------------------
__global__ __launch_bounds__(256)
void vq_refine(const float* __restrict__ cb, float* __restrict__ out) {
    int lane = threadIdx.x & 31;
    int n    = blockIdx.x * 8 + (threadIdx.x >> 5);
    const float* dr = g_dist + (size_t)n * KK;

    // 32 strided dists per lane: element i -> k = i*32 + lane (coalesced)
    float d[32];
    #pragma unroll
    for (int i = 0; i < 32; i++) d[i] = dr[i * 32 + lane];

    // packed (distbits, k) min — ascending k scan keeps first index on ties
    ull best = ~0ull;
    #pragma unroll
    for (int i = 0; i < 32; i++) {
        ull p = ((ull)__float_as_uint(d[i]) << 32) | (uint32_t)(i * 32 + lane);
        if (p < best) best = p;
    }
    #pragma unroll
    for (int o = 16; o; o >>= 1) {
        ull v = __shfl_xor_sync(0xffffffffu, best, o);
        if (v < best) best = v;
    }
    float minv = __uint_as_float((uint32_t)(best >> 32));

    float zsq = g_zsq[n];
    float wmaxsq = __int_as_float(g_wsqmax_bits);
    // per-entry bound (inflated): 2.5e-3 * ||z||*||w||max + 5e-4 ; margin = 2*bound
    float bound = fmaf(2.5e-3f, sqrtf(zsq * wmaxsq), 5.0e-4f);
    float thresh = minv + 2.0f * bound;

    int cnt = 0;
    #pragma unroll
    for (int i = 0; i < 32; i++) cnt += (d[i] <= thresh);
    #pragma unroll
    for (int o = 16; o; o >>= 1) cnt += __shfl_xor_sync(0xffffffffu, cnt, o);

    int winner;
    if (cnt == 1) {
        winner = (int)(uint32_t)(best & 0xffffffffULL);
    } else {
        // exact recompute over candidates (enumerated k-ascending)
        const float* zr = g_zT + (size_t)n * DD + lane * 16;
        float4 z0 = ((const float4*)zr)[0];
        float4 z1 = ((const float4*)zr)[1];
        float4 z2 = ((const float4*)zr)[2];
        float4 z3 = ((const float4*)zr)[3];
        ull eb = ~0ull;
        for (int i = 0; i < 32; i++) {
            unsigned m = __ballot_sync(0xffffffffu, d[i] <= thresh);
            while (m) {
                int src = __ffs(m) - 1;
                m &= m - 1;
                int k = i * 32 + src;
                const float* wr = cb + (size_t)k * DD + lane * 16;
                float4 w0 = ((const float4*)wr)[0];
                float4 w1 = ((const float4*)wr)[1];
                float4 w2 = ((const float4*)wr)[2];
                float4 w3 = ((const float4*)wr)[3];
                float s = 0.f;
                s = fmaf(z0.x, w0.x, s); s = fmaf(z0.y, w0.y, s);
                s = fmaf(z0.z, w0.z, s); s = fmaf(z0.w, w0.w, s);
                s = fmaf(z1.x, w1.x, s); s = fmaf(z1.y, w1.y, s);
                s = fmaf(z1.z, w1.z, s); s = fmaf(z1.w, w1.w, s);
                s = fmaf(z2.x, w2.x, s); s = fmaf(z2.y, w2.y, s);
                s = fmaf(z2.z, w2.z, s); s = fmaf(z2.w, w2.w, s);
                s = fmaf(z3.x, w3.x, s); s = fmaf(z3.y, w3.y, s);
                s = fmaf(z3.z, w3.z, s); s = fmaf(z3.w, w3.w, s);
                #pragma unroll
                for (int o = 16; o; o >>= 1) s += __shfl_xor_sync(0xffffffffu, s, o);
                float dist = __fadd_rn(__fsub_rn(zsq, __fmul_rn(2.0f, s)), __ldg(&g_wsq[k]));
                ull p = ((ull)__float_as_uint(dist) << 32) | (uint32_t)k;
                if (p < eb) eb = p;   // k ascending -> first-index ties
            }
        }
        winner = (int)(uint32_t)(eb & 0xffffffffULL);
    }

    if (lane == 0) {
        g_idx[n] = winner;
        out[(size_t)NQ + n] = (float)winner;
    }
}

// ---------------- K3: gather z_q, write z_q_st, loss (vectorized) -------------
__global__ void gather_out(const float* __restrict__ z, float* __restrict__ out) {
    int bd = blockIdx.x;
    int b  = bd >> 9;
    int d  = bd & (DD - 1);
    __shared__ float row[KK];
    ((float4*)row)[threadIdx.x] = ((const float4*)(g_cbT + (size_t)d * KK))[threadIdx.x];
    __syncthreads();

    size_t base = ((size_t)b * DD + d) * TT;
    int t = threadIdx.x * 8;
    int4  i0 = *(const int4*)(g_idx + b * TT + t);
    int4  i1 = *(const int4*)(g_idx + b * TT + t + 4);
    float4 z0 = *(const float4*)(z + base + t);
    float4 z1 = *(const float4*)(z + base + t + 4);

    float4 o0, o1;
    double lsum = 0.0;
    {
        float zq, df;
        zq = row[i0.x]; o0.x = __fadd_rn(z0.x, __fsub_rn(zq, z0.x)); df = __fsub_rn(zq, z0.x); lsum += (double)df * df;
        zq = row[i0.y]; o0.y = __fadd_rn(z0.y, __fsub_rn(zq, z0.y)); df = __fsub_rn(zq, z0.y); lsum += (double)df * df;
        zq = row[i0.z]; o0.z = __fadd_rn(z0.z, __fsub_rn(zq, z0.z)); df = __fsub_rn(zq, z0.z); lsum += (double)df * df;
        zq = row[i0.w]; o0.w = __fadd_rn(z0.w, __fsub_rn(zq, z0.w)); df = __fsub_rn(zq, z0.w); lsum += (double)df * df;
        zq = row[i1.x]; o1.x = __fadd_rn(z1.x, __fsub_rn(zq, z1.x)); df = __fsub_rn(zq, z1.x); lsum += (double)df * df;
        zq = row[i1.y]; o1.y = __fadd_rn(z1.y, __fsub_rn(zq, z1.y)); df = __fsub_rn(zq, z1.y); lsum += (double)df * df;
        zq = row[i1.z]; o1.z = __fadd_rn(z1.z, __fsub_rn(zq, z1.z)); df = __fsub_rn(zq, z1.z); lsum += (double)df * df;
        zq = row[i1.w]; o1.w = __fadd_rn(z1.w, __fsub_rn(zq, z1.w)); df = __fsub_rn(zq, z1.w); lsum += (double)df * df;
    }
    *(float4*)(out + base + t)     = o0;
    *(float4*)(out + base + t + 4) = o1;

    #pragma unroll
    for (int o = 16; o; o >>= 1) lsum += __shfl_xor_sync(0xffffffffu, lsum, o);
    __shared__ double red[8];
    if ((threadIdx.x & 31) == 0) red[threadIdx.x >> 5] = lsum;
    __syncthreads();
    if (threadIdx.x == 0) {
        double s = 0.0;
        #pragma unroll
        for (int i = 0; i < 8; i++) s += red[i];
        atomicAdd(&g_loss, s);
    }
}

// ---------------- K4: finalize loss ------------------------------------------
__global__ void finalize_loss(float* __restrict__ out) {
    out[(size_t)NQ + NN] = (float)(g_loss * (1.25 / (double)NQ));
}

// ---------------- launch ------------------------------------------------------
extern "C" void kernel_launch(void* const* d_in, const int* in_sizes, int n_in,
                              void* d_out, int out_size) {
    const float* z  = (const float*)d_in[0];   // [16, 512, 2048] fp32
    const float* cb = (const float*)d_in[1];   // [1024, 512] fp32
    float* out = (float*)d_out;                // [z_q_st | indices | loss]

    cudaFuncSetAttribute(vq_pass1, cudaFuncAttributeMaxDynamicSharedMemorySize, DYN_SMEM);

    prep_codebook<<<KK, 128>>>(cb);
    transpose_split<<<dim3(TT / 32, DD / 32, BB), dim3(32, 8)>>>(z);
    compute_zsq<<<NN / 128, 128>>>(z);
    vq_pass1<<<NN / M_TILE, THREADS, DYN_SMEM>>>();
    vq_refine<<<NN / 8, 256>>>(cb, out);
    gather_out<<<BB * DD, 256>>>(z, out);
    finalize_loss<<<1, 1>>>(out);
}

// round 16
// speedup vs baseline: 1.0955x; 1.0955x over previous
#include <cuda_runtime.h>
#include <cuda_bf16.h>
#include <cstdint>

// ---------------- problem constants ----------------
#define BB   16
#define DD   512
#define TT   2048
#define KK   1024
#define NN   (BB*TT)          // 32768
#define NQ   (BB*DD*TT)       // 16777216

// ---------------- pass-1 tiling (bf16 m16n8k16) ----------------
#define M_TILE   128
#define N_TILE   128
#define NT_COUNT (KK / N_TILE)        // 8
#define D_STAGE  32                   // 16 bf16x2 pairs
#define STAGES_PER_NT (DD / D_STAGE)  // 16
#define TOT_STAGES (NT_COUNT * STAGES_PER_NT)  // 128
#define THREADS  256

// smem: [row][d-pair] as uint32 (bf16x2). stride 20 pairs (16 data + 4 pad):
// bank = (r4*20 + q) mod 32 -> {0,20,8,28,16,4,24,12}+q, all 32 distinct.
#define LDP 20
#define PLANE_BYTES (128 * LDP * 4)    // 10240
#define OFF_B PLANE_BYTES
#define BUF_BYTES (2 * PLANE_BYTES)    // 20480
#define DYN_SMEM  (3 * BUF_BYTES)      // 61440 -> 2 CTAs/SM

typedef unsigned long long ull;

// ---------------- PTX helpers (arch-neutral: compute_80+) ----------------
__device__ __forceinline__ uint32_t smem_u32(const void* p) {
    uint32_t a;
    asm("{ .reg .u64 t; cvta.to.shared.u64 t, %1; cvt.u32.u64 %0, t; }" : "=r"(a) : "l"(p));
    return a;
}
#define CP_ASYNC16(dst, src) asm volatile("cp.async.cg.shared.global [%0], [%1], 16;" :: "r"(dst), "l"(src))
#define CP_COMMIT()          asm volatile("cp.async.commit_group;" ::: "memory")
#define CP_WAIT1()           asm volatile("cp.async.wait_group 1;" ::: "memory")
#define CP_WAIT0()           asm volatile("cp.async.wait_group 0;" ::: "memory")

#define MMA_BF16(c0,c1,c2,c3, a0,a1,a2,a3, b0,b1) \
    asm volatile("mma.sync.aligned.m16n8k16.row.col.f32.bf16.bf16.f32 " \
        "{%0,%1,%2,%3}, {%4,%5,%6,%7}, {%8,%9}, {%0,%1,%2,%3};" \
        : "+f"(c0), "+f"(c1), "+f"(c2), "+f"(c3) \
        : "r"(a0), "r"(a1), "r"(a2), "r"(a3), "r"(b0), "r"(b1))

// ---------------- device scratch (static: allocation-free rule) ---------------
__device__ __nv_bfloat16 g_zBf[(size_t)NQ];   // 32 MB: bf16 z, [n][d]
__device__ float  g_zT[(size_t)NQ];           // 64 MB: exact fp32 z, [n][d]
__device__ float  g_dist[(size_t)NN*KK];      // 128 MB: approx dists
__device__ __nv_bfloat16 g_cbBf[KK * DD];     // 1 MB: bf16 codebook [k][d]
__device__ float  g_cbT[DD * KK];             // gather cache [d][k]
__device__ float  g_wsq[KK];
__device__ float  g_zsq[NN];
__device__ int    g_idx[NN];
__device__ int    g_wsqmax_bits;              // max wsq (float bits)
__device__ double g_loss;

// ---------------- K0a: codebook prep ------------------------------------------
__global__ void prep_codebook(const float* __restrict__ cb) {
    int k   = blockIdx.x;
    int tid = threadIdx.x;      // 128
    float s = 0.f;
    for (int d = tid; d < DD; d += 128) {
        float v = cb[(size_t)k * DD + d];
        g_cbT[(size_t)d * KK + k]  = v;
        g_cbBf[(size_t)k * DD + d] = __float2bfloat16(v);
        s += v * v;
    }
    #pragma unroll
    for (int o = 16; o; o >>= 1) s += __shfl_xor_sync(0xffffffffu, s, o);
    __shared__ float ws[4];
    if ((tid & 31) == 0) ws[tid >> 5] = s;
    __syncthreads();
    if (tid == 0) {
        float w = (ws[0] + ws[1]) + (ws[2] + ws[3]);
        g_wsq[k] = w;
        atomicMax(&g_wsqmax_bits, __float_as_int(w));
        if (k == 0) g_loss = 0.0;
    }
}

// ---------------- K0b: z -> exact transposed ([n][d]) + bf16 plane ------------
__global__ void transpose_split(const float* __restrict__ z) {
    __shared__ float tile[32][33];
    int b  = blockIdx.z;
    int d0 = blockIdx.y * 32;
    int t0 = blockIdx.x * 32;
    int tx = threadIdx.x, ty = threadIdx.y;
    #pragma unroll
    for (int i = ty; i < 32; i += 8)
        tile[i][tx] = z[((size_t)b * DD + d0 + i) * TT + t0 + tx];
    __syncthreads();
    #pragma unroll
    for (int i = ty; i < 32; i += 8) {
        float v = tile[tx][i];
        size_t off = (size_t)(b * TT + t0 + i) * DD + d0 + tx;
        g_zT[off]  = v;
        g_zBf[off] = __float2bfloat16(v);
    }
}

// ---------------- K0c: per-row |z|^2 ------------------------------------------
__global__ void compute_zsq(const float* __restrict__ z) {
    int n0 = blockIdx.x * 128;
    int b  = n0 >> 11;
    int t  = (n0 & (TT - 1)) + threadIdx.x;
    const float* zb = z + (size_t)b * DD * TT + t;
    float s0 = 0.f, s1 = 0.f, s2 = 0.f, s3 = 0.f;
    #pragma unroll 4
    for (int d = 0; d < DD; d += 4) {
        float v0 = zb[(size_t)(d + 0) * TT];
        float v1 = zb[(size_t)(d + 1) * TT];
        float v2 = zb[(size_t)(d + 2) * TT];
        float v3 = zb[(size_t)(d + 3) * TT];
        s0 = fmaf(v0, v0, s0);
        s1 = fmaf(v1, v1, s1);
        s2 = fmaf(v2, v2, s2);
        s3 = fmaf(v3, v3, s3);
    }
    g_zsq[n0 + threadIdx.x] = (s0 + s1) + (s2 + s3);
}

// ---------------- K1: pass-1 bf16 GEMM -> approx dist matrix ------------------
// 3-buffer cp.async pipeline, one __syncthreads per stage.
__global__ __launch_bounds__(THREADS, 2)
void vq_pass1()
{
    extern __shared__ char dyn[];

    const uint32_t dynb = smem_u32(dyn);
    int tid  = threadIdx.x;
    int lane = tid & 31;
    int wid  = tid >> 5;
    int q    = lane & 3;
    int r4   = lane >> 2;
    int warpM  = (wid & 3) * 32;   // 4 M-bands of 32
    int warpNb = wid >> 2;         // 2 N-bands
    int warpN  = warpNb * 64;

    int n0 = blockIdx.x * M_TILE;  // grid = 256 (one wave at 2 CTAs/SM)

    float zsqr[4];   // rows warpM + 16mi + 8h + r4
    #pragma unroll
    for (int mi = 0; mi < 2; mi++)
        #pragma unroll
        for (int h = 0; h < 2; h++)
            zsqr[mi * 2 + h] = g_zsq[n0 + warpM + 16 * mi + 8 * h + r4];

    float acc[2][8][4];   // (mi, nf, e) = 64 floats
    #pragma unroll
    for (int mi = 0; mi < 2; mi++)
        #pragma unroll
        for (int nf = 0; nf < 8; nf++)
            #pragma unroll
            for (int e = 0; e < 4; e++) acc[mi][nf][e] = 0.f;

    // cp.async decomposition: 512 16B chunks per operand, 2/thread each
    int cRow[2], cChk[2];
    #pragma unroll
    for (int i = 0; i < 2; i++) {
        int u = tid + i * 256;
        cRow[i] = u >> 2;          // 0..127
        cChk[i] = u & 3;           // 16B chunk (8 bf16 = 8 d)
    }

    auto load_stage = [&](int gs, int buf) {
        int d0  = (gs & (STAGES_PER_NT - 1)) * D_STAGE;
        int kb0 = (gs >> 4) * N_TILE;
        uint32_t bb = dynb + buf * BUF_BYTES;
        #pragma unroll
        for (int i = 0; i < 2; i++) {
            CP_ASYNC16(bb + cRow[i] * (LDP * 4) + cChk[i] * 16,
                       g_zBf + (size_t)(n0 + cRow[i]) * DD + d0 + cChk[i] * 8);
            CP_ASYNC16(bb + OFF_B + cRow[i] * (LDP * 4) + cChk[i] * 16,
                       g_cbBf + (size_t)(kb0 + cRow[i]) * DD + d0 + cChk[i] * 8);
        }
        CP_COMMIT();
    };

    load_stage(0, 0);
    load_stage(1, 1);

    #pragma unroll 1
    for (int gs = 0; gs < TOT_STAGES; gs++) {
        if (gs + 1 < TOT_STAGES) { CP_WAIT1(); } else { CP_WAIT0(); }
        __syncthreads();   // stage gs visible; all reads of buf (gs-1)%3 done
        if (gs + 2 < TOT_STAGES) load_stage(gs + 2, (gs + 2) % 3);

        int cur = gs % 3;
        const uint32_t* As = (const uint32_t*)(dyn + cur * BUF_BYTES);
        const uint32_t* Bs = (const uint32_t*)(dyn + cur * BUF_BYTES + OFF_B);

        #pragma unroll
        for (int j = 0; j < 2; j++) {       // two k16 MMAs cover the 32-d stage
            int pj = 8 * j;
            uint32_t a0[2], a1[2], a2[2], a3[2];
            #pragma unroll
            for (int mi = 0; mi < 2; mi++) {
                int rm = warpM + 16 * mi + r4;
                a0[mi] = As[rm * LDP + pj + q];
                a1[mi] = As[(rm + 8) * LDP + pj + q];
                a2[mi] = As[rm * LDP + pj + q + 4];
                a3[mi] = As[(rm + 8) * LDP + pj + q + 4];
            }
            #pragma unroll
            for (int nf = 0; nf < 8; nf++) {
                int nn = warpN + 8 * nf + r4;
                uint32_t b0 = Bs[nn * LDP + pj + q];
                uint32_t b1 = Bs[nn * LDP + pj + q + 4];
                #pragma unroll
                for (int mi = 0; mi < 2; mi++) {
                    float* c = acc[mi][nf];
                    MMA_BF16(c[0], c[1], c[2], c[3],
                             a0[mi], a1[mi], a2[mi], a3[mi], b0, b1);
                }
            }
        }

        // n-tile boundary: store dists, reset acc (register-only)
        if ((gs & (STAGES_PER_NT - 1)) == STAGES_PER_NT - 1) {
            int kb0 = (gs >> 4) * N_TILE;
            #pragma unroll
            for (int mi = 0; mi < 2; mi++) {
                #pragma unroll
                for (int h = 0; h < 2; h++) {
                    int n = n0 + warpM + 16 * mi + 8 * h + r4;
                    float zs = zsqr[mi * 2 + h];
                    #pragma unroll
                    for (int nf = 0; nf < 8; nf++) {
                        int col = kb0 + warpN + 8 * nf + 2 * q;
                        float w0 = __ldg(&g_wsq[col]);
                        float w1 = __ldg(&g_wsq[col + 1]);
                        float v0 = __fadd_rn(__fsub_rn(zs, __fmul_rn(2.0f, acc[mi][nf][2 * h + 0])), w0);
                        float v1 = __fadd_rn(__fsub_rn(zs, __fmul_rn(2.0f, acc[mi][nf][2 * h + 1])), w1);
                        *(float2*)(g_dist + (size_t)n * KK + col) = make_float2(v0, v1);
                    }
                }
            }
            #pragma unroll
            for (int mi = 0; mi < 2; mi++)
                #pragma unroll
                for (int nf = 0; nf < 8; nf++)
                    #pragma unroll
                    for (int e = 0; e < 4; e++) acc[mi][nf][e] = 0.f;
        }
    }
}

// ---------------- K2: refine — warp-per-row exact argmin ----------------------
__global__ __launch_bounds__(256)
void vq_refine(const float* __restrict__ cb, float* __restrict__ out) {
    int lane = threadIdx.x & 31;
    int n    = blockIdx.x * 8 + (threadIdx.x >> 5);
    const float* dr = g_dist + (size_t)n * KK;

    // 32 strided dists per lane: element i -> k = i*32 + lane (coalesced)
    float d[32];
    #pragma unroll
    for (int i = 0; i < 32; i++) d[i] = dr[i * 32 + lane];

    // packed (distbits, k) min — ascending k keeps first index on ties
    ull best = ~0ull;
    #pragma unroll
    for (int i = 0; i < 32; i++) {
        ull p = ((ull)__float_as_uint(d[i]) << 32) | (uint32_t)(i * 32 + lane);
        if (p < best) best = p;
    }
    #pragma unroll
    for (int o = 16; o; o >>= 1) {
        ull v = __shfl_xor_sync(0xffffffffu, best, o);
        if (v < best) best = v;
    }
    float minv = __uint_as_float((uint32_t)(best >> 32));

    float zsq = g_zsq[n];
    float wmaxsq = __int_as_float(g_wsqmax_bits);
    // bf16 per-dist bound: 2^-6*||z||*||w||max ~ 1.56e-2*sqrt -> inflated 2e-2 + 1e-3
    float bound = fmaf(2.0e-2f, sqrtf(zsq * wmaxsq), 1.0e-3f);
    float thresh = minv + 2.0f * bound;

    int cnt = 0;
    #pragma unroll
    for (int i = 0; i < 32; i++) cnt += (d[i] <= thresh);
    #pragma unroll
    for (int o = 16; o; o >>= 1) cnt += __shfl_xor_sync(0xffffffffu, cnt, o);

    int winner;
    if (cnt == 1) {
        winner = (int)(uint32_t)(best & 0xffffffffULL);
    } else {
        // exact fp32 recompute over candidates (k-ascending enumeration)
        const float* zr = g_zT + (size_t)n * DD + lane * 16;
        float4 z0 = ((const float4*)zr)[0];
        float4 z1 = ((const float4*)zr)[1];
        float4 z2 = ((const float4*)zr)[2];
        float4 z3 = ((const float4*)zr)[3];
        ull eb = ~0ull;
        for (int i = 0; i < 32; i++) {
            unsigned m = __ballot_sync(0xffffffffu, d[i] <= thresh);
            while (m) {
                int src = __ffs(m) - 1;
                m &= m - 1;
                int k = i * 32 + src;
                const float* wr = cb + (size_t)k * DD + lane * 16;
                float4 w0 = ((const float4*)wr)[0];
                float4 w1 = ((const float4*)wr)[1];
                float4 w2 = ((const float4*)wr)[2];
                float4 w3 = ((const float4*)wr)[3];
                float s = 0.f;
                s = fmaf(z0.x, w0.x, s); s = fmaf(z0.y, w0.y, s);
                s = fmaf(z0.z, w0.z, s); s = fmaf(z0.w, w0.w, s);
                s = fmaf(z1.x, w1.x, s); s = fmaf(z1.y, w1.y, s);
                s = fmaf(z1.z, w1.z, s); s = fmaf(z1.w, w1.w, s);
                s = fmaf(z2.x, w2.x, s); s = fmaf(z2.y, w2.y, s);
                s = fmaf(z2.z, w2.z, s); s = fmaf(z2.w, w2.w, s);
                s = fmaf(z3.x, w3.x, s); s = fmaf(z3.y, w3.y, s);
                s = fmaf(z3.z, w3.z, s); s = fmaf(z3.w, w3.w, s);
                #pragma unroll
                for (int o = 16; o; o >>= 1) s += __shfl_xor_sync(0xffffffffu, s, o);
                float dist = __fadd_rn(__fsub_rn(zsq, __fmul_rn(2.0f, s)), __ldg(&g_wsq[k]));
                ull p = ((ull)__float_as_uint(dist) << 32) | (uint32_t)k;
                if (p < eb) eb = p;   // k ascending -> first-index ties
            }
        }
        winner = (int)(uint32_t)(eb & 0xffffffffULL);
    }

    if (lane == 0) {
        g_idx[n] = winner;
        out[(size_t)NQ + n] = (float)winner;
    }
}

// ---------------- K3: gather z_q, write z_q_st, loss (vectorized) -------------
__global__ void gather_out(const float* __restrict__ z, float* __restrict__ out) {
    int bd = blockIdx.x;
    int b  = bd >> 9;
    int d  = bd & (DD - 1);
    __shared__ float row[KK];
    ((float4*)row)[threadIdx.x] = ((const float4*)(g_cbT + (size_t)d * KK))[threadIdx.x];
    __syncthreads();

    size_t base = ((size_t)b * DD + d) * TT;
    int t = threadIdx.x * 8;
    int4  i0 = *(const int4*)(g_idx + b * TT + t);
    int4  i1 = *(const int4*)(g_idx + b * TT + t + 4);
    float4 z0 = *(const float4*)(z + base + t);
    float4 z1 = *(const float4*)(z + base + t + 4);

    float4 o0, o1;
    double lsum = 0.0;
    {
        float zq, df;
        zq = row[i0.x]; o0.x = __fadd_rn(z0.x, __fsub_rn(zq, z0.x)); df = __fsub_rn(zq, z0.x); lsum += (double)df * df;
        zq = row[i0.y]; o0.y = __fadd_rn(z0.y, __fsub_rn(zq, z0.y)); df = __fsub_rn(zq, z0.y); lsum += (double)df * df;
        zq = row[i0.z]; o0.z = __fadd_rn(z0.z, __fsub_rn(zq, z0.z)); df = __fsub_rn(zq, z0.z); lsum += (double)df * df;
        zq = row[i0.w]; o0.w = __fadd_rn(z0.w, __fsub_rn(zq, z0.w)); df = __fsub_rn(zq, z0.w); lsum += (double)df * df;
        zq = row[i1.x]; o1.x = __fadd_rn(z1.x, __fsub_rn(zq, z1.x)); df = __fsub_rn(zq, z1.x); lsum += (double)df * df;
        zq = row[i1.y]; o1.y = __fadd_rn(z1.y, __fsub_rn(zq, z1.y)); df = __fsub_rn(zq, z1.y); lsum += (double)df * df;
        zq = row[i1.z]; o1.z = __fadd_rn(z1.z, __fsub_rn(zq, z1.z)); df = __fsub_rn(zq, z1.z); lsum += (double)df * df;
        zq = row[i1.w]; o1.w = __fadd_rn(z1.w, __fsub_rn(zq, z1.w)); df = __fsub_rn(zq, z1.w); lsum += (double)df * df;
    }
    *(float4*)(out + base + t)     = o0;
    *(float4*)(out + base + t + 4) = o1;

    #pragma unroll
    for (int o = 16; o; o >>= 1) lsum += __shfl_xor_sync(0xffffffffu, lsum, o);
    __shared__ double red[8];
    if ((threadIdx.x & 31) == 0) red[threadIdx.x >> 5] = lsum;
    __syncthreads();
    if (threadIdx.x == 0) {
        double s = 0.0;
        #pragma unroll
        for (int i = 0; i < 8; i++) s += red[i];
        atomicAdd(&g_loss, s);
    }
}

// ---------------- K4: finalize loss ------------------------------------------
__global__ void finalize_loss(float* __restrict__ out) {
    out[(size_t)NQ + NN] = (float)(g_loss * (1.25 / (double)NQ));
}

// ---------------- launch ------------------------------------------------------
extern "C" void kernel_launch(void* const* d_in, const int* in_sizes, int n_in,
                              void* d_out, int out_size) {
    const float* z  = (const float*)d_in[0];   // [16, 512, 2048] fp32
    const float* cb = (const float*)d_in[1];   // [1024, 512] fp32
    float* out = (float*)d_out;                // [z_q_st | indices | loss]

    cudaFuncSetAttribute(vq_pass1, cudaFuncAttributeMaxDynamicSharedMemorySize, DYN_SMEM);

    prep_codebook<<<KK, 128>>>(cb);
    transpose_split<<<dim3(TT / 32, DD / 32, BB), dim3(32, 8)>>>(z);
    compute_zsq<<<NN / 128, 128>>>(z);
    vq_pass1<<<NN / M_TILE, THREADS, DYN_SMEM>>>();
    vq_refine<<<NN / 8, 256>>>(cb, out);
    gather_out<<<BB * DD, 256>>>(z, out);
    finalize_loss<<<1, 1>>>(out);
}